// round 8
// baseline (speedup 1.0000x reference)
#include <cuda_runtime.h>
#include <cuda_fp16.h>
#include <cstdint>

// Problem shapes (fixed by the dataset)
constexpr int M_TOK = 16384;   // b*s = 4*4096
constexpr int KDIM  = 2048;    // h
constexpr int NTOT  = 192;     // q|k|v concatenated

// GEMM tiling — BM=64 for 2 CTAs/SM
constexpr int BM = 64;
constexpr int BN = 192;
constexpr int BK = 32;
constexpr int PAD_K = 40;      // row = 80 B (16B-aligned, LDSM conflict-free)
constexpr int NCHUNK = KDIM / BK;  // 64

constexpr int SM_X = BM * PAD_K;   // 2560 fp16
constexpr int SM_W = BN * PAD_K;   // 7680 fp16

constexpr int XBUF_STRIDE_B = SM_X * 2;           // 5120 B
constexpr int WBUF_STRIDE_B = SM_W * 2;           // 15360 B
constexpr int OFF_X_B = 0;
constexpr int OFF_W_B = 2 * XBUF_STRIDE_B;        // 10240
constexpr int GEMM_SMEM = 2 * XBUF_STRIDE_B + 2 * WBUF_STRIDE_B;  // 40960 B

// Epilogue staging: C[64][200] fp32 (aliases the GEMM buffers)
constexpr int C_STRIDE = 200;                     // floats; pad vs 192
constexpr int EPI_SMEM = BM * C_STRIDE * 4;       // 51200 B
constexpr int SMEM_BYTES = (GEMM_SMEM > EPI_SMEM) ? GEMM_SMEM : EPI_SMEM;  // 51200

// Scratch
__device__ __half g_Wt[(size_t)NTOT * KDIM];      // [n][k], fp16

// ---------------------------------------------------------------- helpers
__device__ __forceinline__ void mma16816(float (&c)[4], const uint32_t (&a)[4],
                                         uint32_t b0, uint32_t b1) {
    asm volatile(
        "mma.sync.aligned.m16n8k16.row.col.f32.f16.f16.f32 "
        "{%0,%1,%2,%3}, {%4,%5,%6,%7}, {%8,%9}, {%0,%1,%2,%3};\n"
        : "+f"(c[0]), "+f"(c[1]), "+f"(c[2]), "+f"(c[3])
        : "r"(a[0]), "r"(a[1]), "r"(a[2]), "r"(a[3]), "r"(b0), "r"(b1));
}
__device__ __forceinline__ void ldsm4(uint32_t (&r)[4], uint32_t addr) {
    asm volatile("ldmatrix.sync.aligned.m8n8.x4.shared.b16 {%0,%1,%2,%3}, [%4];"
                 : "=r"(r[0]), "=r"(r[1]), "=r"(r[2]), "=r"(r[3]) : "r"(addr));
}
__device__ __forceinline__ void cp_async16(uint32_t dst, const void* src) {
    asm volatile("cp.async.cg.shared.global [%0], [%1], 16;\n" :: "r"(dst), "l"(src) : "memory");
}
__device__ __forceinline__ void cp_commit() {
    asm volatile("cp.async.commit_group;\n" ::: "memory");
}
__device__ __forceinline__ uint32_t cvt_f16x2(float a, float b) {  // pack (a lo, b hi)
    uint32_t r;
    asm("cvt.rn.f16x2.f32 %0, %1, %2;" : "=r"(r) : "f"(b), "f"(a));
    return r;
}
__device__ __forceinline__ float ex2f(float x) {
    float y;
    asm("ex2.approx.ftz.f32 %0, %1;" : "=f"(y) : "f"(x));
    return y;
}

// ---------------------------------------------------------------- prep_w
// Tiled transpose W(h,z) -> Wt[n][k], fp16. 192 blocks x 256.
__global__ void prep_w(const float* __restrict__ Wq,
                       const float* __restrict__ Wk,
                       const float* __restrict__ Wv) {
    __shared__ float s[32][65];
    const int m  = blockIdx.x / 64;          // matrix
    const int k0 = (blockIdx.x % 64) * 32;   // k tile
    const float* W = (m == 0) ? Wq : ((m == 1) ? Wk : Wv);
    const int t = threadIdx.x;
#pragma unroll
    for (int i = 0; i < 8; i++) {
        int u = t + i * 256;
        int kl = u >> 6, z = u & 63;
        s[kl][z] = W[(size_t)(k0 + kl) * 64 + z];   // coalesced read
    }
    __syncthreads();
#pragma unroll
    for (int i = 0; i < 8; i++) {
        int u = t + i * 256;
        int z = u >> 5, kl = u & 31;
        size_t o = (size_t)(m * 64 + z) * KDIM + k0 + kl;  // coalesced write
        g_Wt[o] = __float2half_rn(s[kl][z]);
    }
}

// ---------------------------------------------------------------- fused GEMM + attention
// Each CTA: qkv = X_tile * W^T (HMMA), then per-token softmax-attention,
// writing out[64 tokens x 64] directly.
__global__ void __launch_bounds__(256, 2)
fused_kernel(const float* __restrict__ X, float* __restrict__ out) {
    extern __shared__ __half smem[];
    const uint32_t sbase = (uint32_t)__cvta_generic_to_shared(smem);

    const int tid  = threadIdx.x;
    const int lane = tid & 31;
    const int wid  = tid >> 5;
    const int g    = lane >> 2;
    const int tig  = lane & 3;
    const int warp_m = (wid & 1) * 32;     // 2 warp rows of 32
    const int warp_n = (wid >> 1) * 48;    // 4 warp cols of 48
    const int m0 = blockIdx.x * BM;

    // ldmatrix lane-address components
    const int lrow = lane & 7;
    const int lbit3 = (lane >> 3) & 1;
    const int lbit4 = (lane >> 4) & 1;

    uint32_t aA[2];
#pragma unroll
    for (int mt = 0; mt < 2; mt++) {
        int row = warp_m + mt * 16 + lrow + lbit3 * 8;
        aA[mt] = sbase + OFF_X_B + (uint32_t)row * 80u + (uint32_t)lbit4 * 16u;
    }
    uint32_t bA[3];
#pragma unroll
    for (int p = 0; p < 3; p++) {
        int row = warp_n + p * 16 + lrow + lbit4 * 8;
        bA[p] = sbase + OFF_W_B + (uint32_t)row * 80u + (uint32_t)lbit3 * 16u;
    }

    // X load/store: 4 threads per row, 8 consecutive floats each
    const int xr = tid >> 2;              // 0..63
    const int xk = (tid & 3) * 8;         // 0,8,16,24
    const uint32_t xsts = sbase + OFF_X_B + (uint32_t)xr * 80u + (uint32_t)xk * 2u;
    const float* xsrc_row = X + (size_t)(m0 + xr) * KDIM + xk;

    const uint32_t wdst0 = sbase + OFF_W_B;

    float acc[2][6][4];
#pragma unroll
    for (int mt = 0; mt < 2; mt++)
#pragma unroll
        for (int nt = 0; nt < 6; nt++)
#pragma unroll
            for (int r = 0; r < 4; r++) acc[mt][nt][r] = 0.f;

    float4 xf[2];

    auto convert_sts = [&](uint32_t dOff) {
        uint32_t hw[4];
        hw[0] = cvt_f16x2(xf[0].x, xf[0].y);
        hw[1] = cvt_f16x2(xf[0].z, xf[0].w);
        hw[2] = cvt_f16x2(xf[1].x, xf[1].y);
        hw[3] = cvt_f16x2(xf[1].z, xf[1].w);
        asm volatile("st.shared.v4.b32 [%0], {%1,%2,%3,%4};" ::
                     "r"(xsts + dOff), "r"(hw[0]), "r"(hw[1]), "r"(hw[2]), "r"(hw[3]));
    };

    auto ldg_x = [&](int c) {
        const float4* p = reinterpret_cast<const float4*>(xsrc_row + (size_t)c * BK);
        xf[0] = p[0]; xf[1] = p[1];
    };

    auto issue_w = [&](int c) {
        const size_t koff = (size_t)c * BK;
        const uint32_t dOff = (uint32_t)(c & 1) * WBUF_STRIDE_B;
#pragma unroll
        for (int r = 0; r < 3; r++) {
            int u = tid + r * 256;
            int n = u >> 2, q = u & 3;
            uint32_t d = wdst0 + dOff + (uint32_t)n * 80u + (uint32_t)q * 16u;
            cp_async16(d, g_Wt + (size_t)n * KDIM + koff + q * 8);
        }
        cp_commit();
    };

    // --- prologue ---
    issue_w(0);
    ldg_x(0);
    convert_sts(0);
    ldg_x(1);
    asm volatile("cp.async.wait_group 0;\n" ::: "memory");
    __syncthreads();

#pragma unroll 1
    for (int c = 0; c < NCHUNK; ++c) {
        const uint32_t xOff = (uint32_t)(c & 1) * XBUF_STRIDE_B;
        const uint32_t wOff = (uint32_t)(c & 1) * WBUF_STRIDE_B;

        if (c + 1 < NCHUNK) convert_sts((uint32_t)((c + 1) & 1) * XBUF_STRIDE_B);
        if (c + 2 < NCHUNK) ldg_x(c + 2);
        if (c + 1 < NCHUNK) issue_w(c + 1);

#pragma unroll
        for (int kk2 = 0; kk2 < 2; kk2++) {
            const uint32_t kb = kk2 * 32;

            uint32_t ah[2][4], bh[3][4];
#pragma unroll
            for (int mt = 0; mt < 2; mt++) ldsm4(ah[mt], aA[mt] + xOff + kb);
#pragma unroll
            for (int p = 0; p < 3; p++)    ldsm4(bh[p], bA[p] + wOff + kb);

#pragma unroll
            for (int mt = 0; mt < 2; mt++)
#pragma unroll
                for (int nt = 0; nt < 6; nt++)
                    mma16816(acc[mt][nt], ah[mt],
                             bh[nt >> 1][(nt & 1) * 2], bh[nt >> 1][(nt & 1) * 2 + 1]);
        }

        if (c + 1 < NCHUNK) {
            asm volatile("cp.async.wait_group 0;\n" ::: "memory");
            __syncthreads();
        }
    }

    // ---------------- fused epilogue: stage C, then per-token attention ----
    __syncthreads();                     // all LDSM reads of smem done
    float* sC = reinterpret_cast<float*>(smem);   // [64][C_STRIDE]

#pragma unroll
    for (int mt = 0; mt < 2; mt++) {
#pragma unroll
        for (int nt = 0; nt < 6; nt++) {
            int r  = warp_m + mt * 16 + g;
            int cn = warp_n + nt * 8 + 2 * tig;
            *reinterpret_cast<float2*>(sC + r * C_STRIDE + cn) =
                make_float2(acc[mt][nt][0], acc[mt][nt][1]);
            *reinterpret_cast<float2*>(sC + (r + 8) * C_STRIDE + cn) =
                make_float2(acc[mt][nt][2], acc[mt][nt][3]);
        }
    }
    __syncthreads();

    // attention: softmax over j of q_i*k_j, weighted sum of v_j.
    // No max-subtraction needed: |q·k| <~ 30, well within fp32 exp range,
    // and softmax is shift-invariant.
    const int tl = tid >> 6;       // 0..3 (token within group)
    const int i  = tid & 63;       // output lane
#pragma unroll 1
    for (int pass = 0; pass < 16; pass++) {
        const int tok = pass * 4 + tl;
        const float* row = sC + tok * C_STRIDE;
        const float q = row[i] * 1.4426950408889634f;   // fold log2(e)
        float s = 0.f, num = 0.f;
#pragma unroll
        for (int j = 0; j < 64; j++) {
            float e = ex2f(q * row[64 + j]);
            s += e;
            num = fmaf(e, row[128 + j], num);
        }
        out[(size_t)(m0 + tok) * 64 + i] = num / s;
    }
}

// ----------------------------------------------------------------
extern "C" void kernel_launch(void* const* d_in, const int* in_sizes, int n_in,
                              void* d_out, int out_size) {
    const float* X  = (const float*)d_in[0];
    const float* Wq = (const float*)d_in[1];
    const float* Wk = (const float*)d_in[2];
    const float* Wv = (const float*)d_in[3];
    float* out = (float*)d_out;

    cudaFuncSetAttribute(fused_kernel, cudaFuncAttributeMaxDynamicSharedMemorySize,
                         SMEM_BYTES);

    prep_w<<<192, 256>>>(Wq, Wk, Wv);
    fused_kernel<<<M_TOK / BM, 256, SMEM_BYTES>>>(X, out);
}

// round 9
// speedup vs baseline: 1.0363x; 1.0363x over previous
#include <cuda_runtime.h>
#include <cuda_fp16.h>
#include <cstdint>

// Problem shapes (fixed by the dataset)
constexpr int M_TOK = 16384;   // b*s
constexpr int KDIM  = 2048;    // h
constexpr int NTOT  = 192;     // q|k|v

// GEMM tiling — BM=64, 384 threads (12 warps: 2 x 6), 2 CTAs/SM
constexpr int BM = 64;
constexpr int BN = 192;
constexpr int BK = 32;
constexpr int PAD_K = 40;      // row = 80 B (16B-aligned, LDSM conflict-free)
constexpr int NCHUNK = KDIM / BK;  // 64

constexpr int SM_X = BM * PAD_K;   // 2560 fp16
constexpr int SM_W = BN * PAD_K;   // 7680 fp16

constexpr int XBUF_STRIDE_B = SM_X * 2;           // 5120 B
constexpr int WBUF_STRIDE_B = SM_W * 2;           // 15360 B
constexpr int OFF_X_B = 0;
constexpr int OFF_W_B = 2 * XBUF_STRIDE_B;        // 10240
constexpr int SMEM_BYTES = 2 * XBUF_STRIDE_B + 2 * WBUF_STRIDE_B;  // 40960 B

// Scratch
__device__ __half g_Wt[(size_t)NTOT * KDIM];      // [n][k], fp16
__device__ float g_qkv[(size_t)M_TOK * NTOT];

// ---------------------------------------------------------------- helpers
__device__ __forceinline__ void mma16816(float (&c)[4], const uint32_t (&a)[4],
                                         uint32_t b0, uint32_t b1) {
    asm volatile(
        "mma.sync.aligned.m16n8k16.row.col.f32.f16.f16.f32 "
        "{%0,%1,%2,%3}, {%4,%5,%6,%7}, {%8,%9}, {%0,%1,%2,%3};\n"
        : "+f"(c[0]), "+f"(c[1]), "+f"(c[2]), "+f"(c[3])
        : "r"(a[0]), "r"(a[1]), "r"(a[2]), "r"(a[3]), "r"(b0), "r"(b1));
}
__device__ __forceinline__ void ldsm4(uint32_t (&r)[4], uint32_t addr) {
    asm volatile("ldmatrix.sync.aligned.m8n8.x4.shared.b16 {%0,%1,%2,%3}, [%4];"
                 : "=r"(r[0]), "=r"(r[1]), "=r"(r[2]), "=r"(r[3]) : "r"(addr));
}
__device__ __forceinline__ void cp_async16(uint32_t dst, const void* src) {
    asm volatile("cp.async.cg.shared.global [%0], [%1], 16;\n" :: "r"(dst), "l"(src) : "memory");
}
__device__ __forceinline__ void cp_commit() {
    asm volatile("cp.async.commit_group;\n" ::: "memory");
}
__device__ __forceinline__ uint32_t cvt_f16x2(float a, float b) {  // pack (a lo, b hi)
    uint32_t r;
    asm("cvt.rn.f16x2.f32 %0, %1, %2;" : "=r"(r) : "f"(b), "f"(a));
    return r;
}
__device__ __forceinline__ float ex2f(float x) {
    float y;
    asm("ex2.approx.ftz.f32 %0, %1;" : "=f"(y) : "f"(x));
    return y;
}

// ---------------------------------------------------------------- prep_w
__global__ void prep_w(const float* __restrict__ Wq,
                       const float* __restrict__ Wk,
                       const float* __restrict__ Wv) {
    __shared__ float s[32][65];
    const int m  = blockIdx.x / 64;          // matrix
    const int k0 = (blockIdx.x % 64) * 32;   // k tile
    const float* W = (m == 0) ? Wq : ((m == 1) ? Wk : Wv);
    const int t = threadIdx.x;
#pragma unroll
    for (int i = 0; i < 8; i++) {
        int u = t + i * 256;
        int kl = u >> 6, z = u & 63;
        s[kl][z] = W[(size_t)(k0 + kl) * 64 + z];   // coalesced read
    }
    __syncthreads();
#pragma unroll
    for (int i = 0; i < 8; i++) {
        int u = t + i * 256;
        int z = u >> 5, kl = u & 31;
        size_t o = (size_t)(m * 64 + z) * KDIM + k0 + kl;  // coalesced write
        g_Wt[o] = __float2half_rn(s[kl][z]);
    }
}

// ---------------------------------------------------------------- QKV GEMM
// 384 threads (12 warps, 2 m-rows x 6 n-cols of 32), 2 CTAs/SM.
__global__ void __launch_bounds__(384, 2)
qkv_gemm(const float* __restrict__ X) {
    extern __shared__ __half smem[];
    const uint32_t sbase = (uint32_t)__cvta_generic_to_shared(smem);

    const int tid  = threadIdx.x;
    const int lane = tid & 31;
    const int wid  = tid >> 5;            // 0..11
    const int g    = lane >> 2;
    const int tig  = lane & 3;
    const int warp_m = (wid & 1) * 32;    // 2 warp rows of 32
    const int warp_n = (wid >> 1) * 32;   // 6 warp cols of 32
    const int m0 = blockIdx.x * BM;

    // ldmatrix lane-address components
    const int lrow = lane & 7;
    const int lbit3 = (lane >> 3) & 1;
    const int lbit4 = (lane >> 4) & 1;

    uint32_t aA[2];
#pragma unroll
    for (int mt = 0; mt < 2; mt++) {
        int row = warp_m + mt * 16 + lrow + lbit3 * 8;
        aA[mt] = sbase + OFF_X_B + (uint32_t)row * 80u + (uint32_t)lbit4 * 16u;
    }
    uint32_t bA[2];
#pragma unroll
    for (int p = 0; p < 2; p++) {
        int row = warp_n + p * 16 + lrow + lbit4 * 8;
        bA[p] = sbase + OFF_W_B + (uint32_t)row * 80u + (uint32_t)lbit3 * 16u;
    }

    // X load/store: threads 0..255 only; 4 threads per row, 8 floats each
    const int xr = (tid & 255) >> 2;       // 0..63
    const int xk = (tid & 3) * 8;          // 0,8,16,24
    const bool xactive = (tid < 256);
    const uint32_t xsts = sbase + OFF_X_B + (uint32_t)xr * 80u + (uint32_t)xk * 2u;
    const float* xsrc_row = X + (size_t)(m0 + xr) * KDIM + xk;

    const uint32_t wdst0 = sbase + OFF_W_B;

    float acc[2][4][4];
#pragma unroll
    for (int mt = 0; mt < 2; mt++)
#pragma unroll
        for (int nt = 0; nt < 4; nt++)
#pragma unroll
            for (int r = 0; r < 4; r++) acc[mt][nt][r] = 0.f;

    float4 xf[2];

    auto convert_sts = [&](uint32_t dOff) {
        if (!xactive) return;
        uint32_t hw[4];
        hw[0] = cvt_f16x2(xf[0].x, xf[0].y);
        hw[1] = cvt_f16x2(xf[0].z, xf[0].w);
        hw[2] = cvt_f16x2(xf[1].x, xf[1].y);
        hw[3] = cvt_f16x2(xf[1].z, xf[1].w);
        asm volatile("st.shared.v4.b32 [%0], {%1,%2,%3,%4};" ::
                     "r"(xsts + dOff), "r"(hw[0]), "r"(hw[1]), "r"(hw[2]), "r"(hw[3]));
    };

    auto ldg_x = [&](int c) {
        if (!xactive) return;
        const float4* p = reinterpret_cast<const float4*>(xsrc_row + (size_t)c * BK);
        xf[0] = p[0]; xf[1] = p[1];
    };

    auto issue_w = [&](int c) {   // 768 quads over 384 threads x 2
        const size_t koff = (size_t)c * BK;
        const uint32_t dOff = (uint32_t)(c & 1) * WBUF_STRIDE_B;
#pragma unroll
        for (int r = 0; r < 2; r++) {
            int u = tid + r * 384;
            int n = u >> 2, q = u & 3;
            uint32_t d = wdst0 + dOff + (uint32_t)n * 80u + (uint32_t)q * 16u;
            cp_async16(d, g_Wt + (size_t)n * KDIM + koff + q * 8);
        }
        cp_commit();
    };

    // --- prologue ---
    issue_w(0);
    ldg_x(0);
    convert_sts(0);
    ldg_x(1);
    asm volatile("cp.async.wait_group 0;\n" ::: "memory");
    __syncthreads();

#pragma unroll 1
    for (int c = 0; c < NCHUNK; ++c) {
        const uint32_t xOff = (uint32_t)(c & 1) * XBUF_STRIDE_B;
        const uint32_t wOff = (uint32_t)(c & 1) * WBUF_STRIDE_B;

        if (c + 1 < NCHUNK) convert_sts((uint32_t)((c + 1) & 1) * XBUF_STRIDE_B);
        if (c + 2 < NCHUNK) ldg_x(c + 2);
        if (c + 1 < NCHUNK) issue_w(c + 1);

#pragma unroll
        for (int kk2 = 0; kk2 < 2; kk2++) {
            const uint32_t kb = kk2 * 32;

            uint32_t ah[2][4], bh[2][4];
#pragma unroll
            for (int mt = 0; mt < 2; mt++) ldsm4(ah[mt], aA[mt] + xOff + kb);
#pragma unroll
            for (int p = 0; p < 2; p++)    ldsm4(bh[p], bA[p] + wOff + kb);

#pragma unroll
            for (int mt = 0; mt < 2; mt++)
#pragma unroll
                for (int nt = 0; nt < 4; nt++)
                    mma16816(acc[mt][nt], ah[mt],
                             bh[nt >> 1][(nt & 1) * 2], bh[nt >> 1][(nt & 1) * 2 + 1]);
        }

        if (c + 1 < NCHUNK) {
            asm volatile("cp.async.wait_group 0;\n" ::: "memory");
            __syncthreads();
        }
    }

    // epilogue: write q|k|v to scratch
#pragma unroll
    for (int mt = 0; mt < 2; mt++) {
#pragma unroll
        for (int nt = 0; nt < 4; nt++) {
            int r  = m0 + warp_m + mt * 16 + g;
            int cn = warp_n + nt * 8 + 2 * tig;
            float2 v0 = make_float2(acc[mt][nt][0], acc[mt][nt][1]);
            float2 v1 = make_float2(acc[mt][nt][2], acc[mt][nt][3]);
            *reinterpret_cast<float2*>(&g_qkv[(size_t)r * NTOT + cn]) = v0;
            *reinterpret_cast<float2*>(&g_qkv[(size_t)(r + 8) * NTOT + cn]) = v1;
        }
    }
}

// ---------------------------------------------------------------- attention
// No max-subtraction (softmax shift-invariant; |q·k| well within fp32 range).
// k/v read from smem as float4.
__global__ void __launch_bounds__(256)
attn_kernel(float* __restrict__ out) {
    __shared__ float4 ks[4][16];
    __shared__ float4 vs[4][16];
    const int tid = threadIdx.x;
    const int tl = tid >> 6;
    const int i  = tid & 63;
    const size_t tok = (size_t)blockIdx.x * 4 + tl;
    const float* base = g_qkv + tok * NTOT;

    float q = base[i] * 1.4426950408889634f;   // fold log2(e)
    float kv_k = base[64 + i];
    float kv_v = base[128 + i];
    reinterpret_cast<float*>(&ks[tl][0])[i] = kv_k;
    reinterpret_cast<float*>(&vs[tl][0])[i] = kv_v;
    __syncthreads();

    float s = 0.f, num = 0.f;
#pragma unroll
    for (int j4 = 0; j4 < 16; j4++) {
        float4 k4 = ks[tl][j4];
        float4 v4 = vs[tl][j4];
        float e0 = ex2f(q * k4.x);
        float e1 = ex2f(q * k4.y);
        float e2 = ex2f(q * k4.z);
        float e3 = ex2f(q * k4.w);
        s += (e0 + e1) + (e2 + e3);
        num = fmaf(e0, v4.x, num);
        num = fmaf(e1, v4.y, num);
        num = fmaf(e2, v4.z, num);
        num = fmaf(e3, v4.w, num);
    }
    out[tok * 64 + i] = num / s;
}

// ----------------------------------------------------------------
extern "C" void kernel_launch(void* const* d_in, const int* in_sizes, int n_in,
                              void* d_out, int out_size) {
    const float* X  = (const float*)d_in[0];
    const float* Wq = (const float*)d_in[1];
    const float* Wk = (const float*)d_in[2];
    const float* Wv = (const float*)d_in[3];
    float* out = (float*)d_out;

    prep_w<<<192, 256>>>(Wq, Wk, Wv);
    qkv_gemm<<<M_TOK / BM, 384, SMEM_BYTES>>>(X);
    attn_kernel<<<M_TOK / 4, 256>>>(out);
}

// round 10
// speedup vs baseline: 1.1574x; 1.1169x over previous
#include <cuda_runtime.h>
#include <cuda_fp16.h>
#include <cstdint>

// Problem shapes (fixed by the dataset)
constexpr int M_TOK = 16384;   // b*s
constexpr int KDIM  = 2048;    // h
constexpr int NTOT  = 192;     // q|k|v

// GEMM tiling — BM=64, BK=64, 256 threads (8 warps: 2x4), 2 CTAs/SM
constexpr int BM = 64;
constexpr int BN = 192;
constexpr int BK = 64;
constexpr int PAD_K = 72;      // row = 144 B (16B-aligned; LDSM conflict-free: 9r+q mod 8 distinct)
constexpr int NCHUNK = KDIM / BK;  // 32

constexpr int SM_X = BM * PAD_K;   // 4608 fp16 = 9216 B
constexpr int SM_W = BN * PAD_K;   // 13824 fp16 = 27648 B

constexpr int XBUF_STRIDE_B = SM_X * 2;           // 9216 B
constexpr int WBUF_STRIDE_B = SM_W * 2;           // 27648 B
constexpr int OFF_X_B = 0;
constexpr int OFF_W_B = 2 * XBUF_STRIDE_B;        // 18432
constexpr int SMEM_BYTES = 2 * XBUF_STRIDE_B + 2 * WBUF_STRIDE_B;  // 73728 B

// Scratch
__device__ __half g_Wt[(size_t)NTOT * KDIM];      // [n][k], fp16
__device__ float g_qkv[(size_t)M_TOK * NTOT];

// ---------------------------------------------------------------- helpers
__device__ __forceinline__ void mma16816(float (&c)[4], const uint32_t (&a)[4],
                                         uint32_t b0, uint32_t b1) {
    asm volatile(
        "mma.sync.aligned.m16n8k16.row.col.f32.f16.f16.f32 "
        "{%0,%1,%2,%3}, {%4,%5,%6,%7}, {%8,%9}, {%0,%1,%2,%3};\n"
        : "+f"(c[0]), "+f"(c[1]), "+f"(c[2]), "+f"(c[3])
        : "r"(a[0]), "r"(a[1]), "r"(a[2]), "r"(a[3]), "r"(b0), "r"(b1));
}
__device__ __forceinline__ void ldsm4(uint32_t (&r)[4], uint32_t addr) {
    asm volatile("ldmatrix.sync.aligned.m8n8.x4.shared.b16 {%0,%1,%2,%3}, [%4];"
                 : "=r"(r[0]), "=r"(r[1]), "=r"(r[2]), "=r"(r[3]) : "r"(addr));
}
__device__ __forceinline__ void cp_async16(uint32_t dst, const void* src) {
    asm volatile("cp.async.cg.shared.global [%0], [%1], 16;\n" :: "r"(dst), "l"(src) : "memory");
}
__device__ __forceinline__ void cp_commit() {
    asm volatile("cp.async.commit_group;\n" ::: "memory");
}
__device__ __forceinline__ uint32_t cvt_f16x2(float a, float b) {  // pack (a lo, b hi)
    uint32_t r;
    asm("cvt.rn.f16x2.f32 %0, %1, %2;" : "=r"(r) : "f"(b), "f"(a));
    return r;
}
__device__ __forceinline__ float ex2f(float x) {
    float y;
    asm("ex2.approx.ftz.f32 %0, %1;" : "=f"(y) : "f"(x));
    return y;
}

// ---------------------------------------------------------------- prep_w
__global__ void prep_w(const float* __restrict__ Wq,
                       const float* __restrict__ Wk,
                       const float* __restrict__ Wv) {
    __shared__ float s[32][65];
    const int m  = blockIdx.x / 64;          // matrix
    const int k0 = (blockIdx.x % 64) * 32;   // k tile
    const float* W = (m == 0) ? Wq : ((m == 1) ? Wk : Wv);
    const int t = threadIdx.x;
#pragma unroll
    for (int i = 0; i < 8; i++) {
        int u = t + i * 256;
        int kl = u >> 6, z = u & 63;
        s[kl][z] = W[(size_t)(k0 + kl) * 64 + z];   // coalesced read
    }
    __syncthreads();
#pragma unroll
    for (int i = 0; i < 8; i++) {
        int u = t + i * 256;
        int z = u >> 5, kl = u & 31;
        size_t o = (size_t)(m * 64 + z) * KDIM + k0 + kl;  // coalesced write
        g_Wt[o] = __float2half_rn(s[kl][z]);
    }
}

// ---------------------------------------------------------------- QKV GEMM
// BK=64 chunks (32 total): half the barriers/waits of BK=32.
__global__ void __launch_bounds__(256, 2)
qkv_gemm(const float* __restrict__ X) {
    extern __shared__ __half smem[];
    const uint32_t sbase = (uint32_t)__cvta_generic_to_shared(smem);

    const int tid  = threadIdx.x;
    const int lane = tid & 31;
    const int wid  = tid >> 5;
    const int g    = lane >> 2;
    const int tig  = lane & 3;
    const int warp_m = (wid & 1) * 32;     // 2 warp rows of 32
    const int warp_n = (wid >> 1) * 48;    // 4 warp cols of 48
    const int m0 = blockIdx.x * BM;

    // ldmatrix lane-address components
    const int lrow = lane & 7;
    const int lbit3 = (lane >> 3) & 1;
    const int lbit4 = (lane >> 4) & 1;

    uint32_t aA[2];
#pragma unroll
    for (int mt = 0; mt < 2; mt++) {
        int row = warp_m + mt * 16 + lrow + lbit3 * 8;
        aA[mt] = sbase + OFF_X_B + (uint32_t)row * 144u + (uint32_t)lbit4 * 16u;
    }
    uint32_t bA[3];
#pragma unroll
    for (int p = 0; p < 3; p++) {
        int row = warp_n + p * 16 + lrow + lbit4 * 8;
        bA[p] = sbase + OFF_W_B + (uint32_t)row * 144u + (uint32_t)lbit3 * 16u;
    }

    // X: 4 threads/row; half h covers float cols (tid&3)*8 + h*32 .. +8
    const int xr = tid >> 2;               // 0..63
    const int xq = tid & 3;
    const uint32_t xsts = sbase + OFF_X_B + (uint32_t)xr * 144u + (uint32_t)xq * 16u;
    const float* xsrc_row = X + (size_t)(m0 + xr) * KDIM + xq * 8;

    const uint32_t wdst0 = sbase + OFF_W_B;

    float acc[2][6][4];
#pragma unroll
    for (int mt = 0; mt < 2; mt++)
#pragma unroll
        for (int nt = 0; nt < 6; nt++)
#pragma unroll
            for (int r = 0; r < 4; r++) acc[mt][nt][r] = 0.f;

    float4 xf[2];   // 8 floats = one half-step

    // convert xf -> fp16, STS to chunk buffer `dOff`, half `h`
    auto convert_sts = [&](uint32_t dOff, int h) {
        uint32_t hw[4];
        hw[0] = cvt_f16x2(xf[0].x, xf[0].y);
        hw[1] = cvt_f16x2(xf[0].z, xf[0].w);
        hw[2] = cvt_f16x2(xf[1].x, xf[1].y);
        hw[3] = cvt_f16x2(xf[1].z, xf[1].w);
        asm volatile("st.shared.v4.b32 [%0], {%1,%2,%3,%4};" ::
                     "r"(xsts + dOff + (uint32_t)h * 64u),
                     "r"(hw[0]), "r"(hw[1]), "r"(hw[2]), "r"(hw[3]));
    };

    // load half h of X chunk c
    auto ldg_x = [&](int c, int h) {
        const float4* p = reinterpret_cast<const float4*>(
            xsrc_row + (size_t)c * BK + h * 32);
        xf[0] = p[0]; xf[1] = p[1];
    };

    auto issue_w = [&](int c) {   // 1536 quads over 256 threads x 6
        const size_t koff = (size_t)c * BK;
        const uint32_t dOff = (uint32_t)(c & 1) * WBUF_STRIDE_B;
#pragma unroll
        for (int r = 0; r < 6; r++) {
            int u = tid + r * 256;
            int n = u >> 3, q = u & 7;
            uint32_t d = wdst0 + dOff + (uint32_t)n * 144u + (uint32_t)q * 16u;
            cp_async16(d, g_Wt + (size_t)n * KDIM + koff + q * 8);
        }
        cp_commit();
    };

    // --- prologue: fill chunk 0, prefetch X(1,h0) ---
    issue_w(0);
    ldg_x(0, 0); convert_sts(0, 0);
    ldg_x(0, 1); convert_sts(0, 1);
    ldg_x(1, 0);
    asm volatile("cp.async.wait_group 0;\n" ::: "memory");
    __syncthreads();

#pragma unroll 1
    for (int c = 0; c < NCHUNK; ++c) {
        const uint32_t xOff = (uint32_t)(c & 1) * XBUF_STRIDE_B;
        const uint32_t wOff = (uint32_t)(c & 1) * WBUF_STRIDE_B;
        const uint32_t xNext = (uint32_t)((c + 1) & 1) * XBUF_STRIDE_B;

        // first half of the next chunk's X (xf holds (c+1,h0))
        if (c + 1 < NCHUNK) {
            convert_sts(xNext, 0);
            ldg_x(c + 1, 1);
            issue_w(c + 1);
        }

        // compute kk2 = 0,1
#pragma unroll
        for (int kk2 = 0; kk2 < 2; kk2++) {
            const uint32_t kb = kk2 * 32;
            uint32_t ah[2][4], bh[3][4];
#pragma unroll
            for (int mt = 0; mt < 2; mt++) ldsm4(ah[mt], aA[mt] + xOff + kb);
#pragma unroll
            for (int p = 0; p < 3; p++)    ldsm4(bh[p], bA[p] + wOff + kb);
#pragma unroll
            for (int mt = 0; mt < 2; mt++)
#pragma unroll
                for (int nt = 0; nt < 6; nt++)
                    mma16816(acc[mt][nt], ah[mt],
                             bh[nt >> 1][(nt & 1) * 2], bh[nt >> 1][(nt & 1) * 2 + 1]);
        }

        // second half of next chunk's X; prefetch (c+2,h0)
        if (c + 1 < NCHUNK) {
            convert_sts(xNext, 1);
            if (c + 2 < NCHUNK) ldg_x(c + 2, 0);
        }

        // compute kk2 = 2,3
#pragma unroll
        for (int kk2 = 2; kk2 < 4; kk2++) {
            const uint32_t kb = kk2 * 32;
            uint32_t ah[2][4], bh[3][4];
#pragma unroll
            for (int mt = 0; mt < 2; mt++) ldsm4(ah[mt], aA[mt] + xOff + kb);
#pragma unroll
            for (int p = 0; p < 3; p++)    ldsm4(bh[p], bA[p] + wOff + kb);
#pragma unroll
            for (int mt = 0; mt < 2; mt++)
#pragma unroll
                for (int nt = 0; nt < 6; nt++)
                    mma16816(acc[mt][nt], ah[mt],
                             bh[nt >> 1][(nt & 1) * 2], bh[nt >> 1][(nt & 1) * 2 + 1]);
        }

        if (c + 1 < NCHUNK) {
            asm volatile("cp.async.wait_group 0;\n" ::: "memory");
            __syncthreads();
        }
    }

    // epilogue: write q|k|v to scratch
#pragma unroll
    for (int mt = 0; mt < 2; mt++) {
#pragma unroll
        for (int nt = 0; nt < 6; nt++) {
            int r  = m0 + warp_m + mt * 16 + g;
            int cn = warp_n + nt * 8 + 2 * tig;
            float2 v0 = make_float2(acc[mt][nt][0], acc[mt][nt][1]);
            float2 v1 = make_float2(acc[mt][nt][2], acc[mt][nt][3]);
            *reinterpret_cast<float2*>(&g_qkv[(size_t)r * NTOT + cn]) = v0;
            *reinterpret_cast<float2*>(&g_qkv[(size_t)(r + 8) * NTOT + cn]) = v1;
        }
    }
}

// ---------------------------------------------------------------- attention
// No max-subtraction (softmax shift-invariant; |q·k| within fp32 exp range).
__global__ void __launch_bounds__(256)
attn_kernel(float* __restrict__ out) {
    __shared__ float4 ks[4][16];
    __shared__ float4 vs[4][16];
    const int tid = threadIdx.x;
    const int tl = tid >> 6;
    const int i  = tid & 63;
    const size_t tok = (size_t)blockIdx.x * 4 + tl;
    const float* base = g_qkv + tok * NTOT;

    float q = base[i] * 1.4426950408889634f;   // fold log2(e)
    reinterpret_cast<float*>(&ks[tl][0])[i] = base[64 + i];
    reinterpret_cast<float*>(&vs[tl][0])[i] = base[128 + i];
    __syncthreads();

    float s = 0.f, num = 0.f;
#pragma unroll
    for (int j4 = 0; j4 < 16; j4++) {
        float4 k4 = ks[tl][j4];
        float4 v4 = vs[tl][j4];
        float e0 = ex2f(q * k4.x);
        float e1 = ex2f(q * k4.y);
        float e2 = ex2f(q * k4.z);
        float e3 = ex2f(q * k4.w);
        s += (e0 + e1) + (e2 + e3);
        num = fmaf(e0, v4.x, num);
        num = fmaf(e1, v4.y, num);
        num = fmaf(e2, v4.z, num);
        num = fmaf(e3, v4.w, num);
    }
    out[tok * 64 + i] = num / s;
}

// ----------------------------------------------------------------
extern "C" void kernel_launch(void* const* d_in, const int* in_sizes, int n_in,
                              void* d_out, int out_size) {
    const float* X  = (const float*)d_in[0];
    const float* Wq = (const float*)d_in[1];
    const float* Wk = (const float*)d_in[2];
    const float* Wv = (const float*)d_in[3];
    float* out = (float*)d_out;

    cudaFuncSetAttribute(qkv_gemm, cudaFuncAttributeMaxDynamicSharedMemorySize,
                         SMEM_BYTES);

    prep_w<<<192, 256>>>(Wq, Wk, Wv);
    qkv_gemm<<<M_TOK / BM, 256, SMEM_BYTES>>>(X);
    attn_kernel<<<M_TOK / 4, 256>>>(out);
}

// round 11
// speedup vs baseline: 1.1939x; 1.0315x over previous
#include <cuda_runtime.h>
#include <cuda_fp16.h>
#include <cstdint>

// Problem shapes (fixed by the dataset)
constexpr int M_TOK = 16384;   // b*s
constexpr int KDIM  = 2048;    // h
constexpr int NTOT  = 192;     // q|k|v

// GEMM tiling — BM=64, BK=64, 256 threads (8 warps: 2x4), 2 CTAs/SM
constexpr int BM = 64;
constexpr int BN = 192;
constexpr int BK = 64;
constexpr int PAD_K = 72;      // row = 144 B (16B-aligned; LDSM conflict-free)
constexpr int NCHUNK = KDIM / BK;  // 32

constexpr int SM_X = BM * PAD_K;   // 4608 fp16 = 9216 B
constexpr int SM_W = BN * PAD_K;   // 13824 fp16 = 27648 B

constexpr int XBUF_STRIDE_B = SM_X * 2;           // 9216 B
constexpr int WBUF_STRIDE_B = SM_W * 2;           // 27648 B
constexpr int OFF_X_B = 0;
constexpr int OFF_W_B = 2 * XBUF_STRIDE_B;        // 18432
// X double-buffered, W TRIPLE-buffered
constexpr int SMEM_BYTES = 2 * XBUF_STRIDE_B + 3 * WBUF_STRIDE_B;  // 101376 B

// Scratch
__device__ __half g_Wt[(size_t)NTOT * KDIM];      // [n][k], fp16
__device__ float g_qkv[(size_t)M_TOK * NTOT];

// ---------------------------------------------------------------- helpers
__device__ __forceinline__ void mma16816(float (&c)[4], const uint32_t (&a)[4],
                                         uint32_t b0, uint32_t b1) {
    asm volatile(
        "mma.sync.aligned.m16n8k16.row.col.f32.f16.f16.f32 "
        "{%0,%1,%2,%3}, {%4,%5,%6,%7}, {%8,%9}, {%0,%1,%2,%3};\n"
        : "+f"(c[0]), "+f"(c[1]), "+f"(c[2]), "+f"(c[3])
        : "r"(a[0]), "r"(a[1]), "r"(a[2]), "r"(a[3]), "r"(b0), "r"(b1));
}
__device__ __forceinline__ void ldsm4(uint32_t (&r)[4], uint32_t addr) {
    asm volatile("ldmatrix.sync.aligned.m8n8.x4.shared.b16 {%0,%1,%2,%3}, [%4];"
                 : "=r"(r[0]), "=r"(r[1]), "=r"(r[2]), "=r"(r[3]) : "r"(addr));
}
__device__ __forceinline__ void cp_async16(uint32_t dst, const void* src) {
    asm volatile("cp.async.cg.shared.global [%0], [%1], 16;\n" :: "r"(dst), "l"(src) : "memory");
}
__device__ __forceinline__ void cp_commit() {
    asm volatile("cp.async.commit_group;\n" ::: "memory");
}
__device__ __forceinline__ uint32_t cvt_f16x2(float a, float b) {  // pack (a lo, b hi)
    uint32_t r;
    asm("cvt.rn.f16x2.f32 %0, %1, %2;" : "=r"(r) : "f"(b), "f"(a));
    return r;
}
__device__ __forceinline__ float ex2f(float x) {
    float y;
    asm("ex2.approx.ftz.f32 %0, %1;" : "=f"(y) : "f"(x));
    return y;
}

// ---------------------------------------------------------------- prep_w
// Vectorized transpose W(h,z) -> Wt[n][k] fp16. 192 blocks x 256 threads.
// Tile: 32 k-rows x 64 z. float4 loads, packed STG.128 stores.
__global__ void prep_w(const float* __restrict__ Wq,
                       const float* __restrict__ Wk,
                       const float* __restrict__ Wv) {
    __shared__ float s[32][65];
    const int m  = blockIdx.x / 64;          // matrix
    const int k0 = (blockIdx.x % 64) * 32;   // k tile
    const float* W = (m == 0) ? Wq : ((m == 1) ? Wk : Wv);
    const int t = threadIdx.x;

    // load 512 float4 (2 per thread), coalesced
#pragma unroll
    for (int i = 0; i < 2; i++) {
        int u = t + i * 256;                 // float4 index
        int kl = u >> 4, c4 = u & 15;
        float4 v = reinterpret_cast<const float4*>(
            W + (size_t)(k0 + kl) * 64)[c4];
        s[kl][c4 * 4 + 0] = v.x;
        s[kl][c4 * 4 + 1] = v.y;
        s[kl][c4 * 4 + 2] = v.z;
        s[kl][c4 * 4 + 3] = v.w;
    }
    __syncthreads();

    // store transposed: thread -> (z = t>>2, kl block = (t&3)*8), 8 halves packed
    const int z   = t >> 2;
    const int klq = (t & 3) * 8;
    uint32_t p[4];
#pragma unroll
    for (int j = 0; j < 4; j++)
        p[j] = cvt_f16x2(s[klq + 2 * j][z], s[klq + 2 * j + 1][z]);
    size_t o = (size_t)(m * 64 + z) * KDIM + k0 + klq;
    *reinterpret_cast<uint4*>(&g_Wt[o]) = make_uint4(p[0], p[1], p[2], p[3]);
}

// ---------------------------------------------------------------- QKV GEMM
// BK=64, triple-buffered W with wait_group 1 (cp.async fully hidden).
__global__ void __launch_bounds__(256, 2)
qkv_gemm(const float* __restrict__ X) {
    extern __shared__ __half smem[];
    const uint32_t sbase = (uint32_t)__cvta_generic_to_shared(smem);

    const int tid  = threadIdx.x;
    const int lane = tid & 31;
    const int wid  = tid >> 5;
    const int g    = lane >> 2;
    const int tig  = lane & 3;
    const int warp_m = (wid & 1) * 32;     // 2 warp rows of 32
    const int warp_n = (wid >> 1) * 48;    // 4 warp cols of 48
    const int m0 = blockIdx.x * BM;

    // ldmatrix lane-address components
    const int lrow = lane & 7;
    const int lbit3 = (lane >> 3) & 1;
    const int lbit4 = (lane >> 4) & 1;

    uint32_t aA[2];
#pragma unroll
    for (int mt = 0; mt < 2; mt++) {
        int row = warp_m + mt * 16 + lrow + lbit3 * 8;
        aA[mt] = sbase + OFF_X_B + (uint32_t)row * 144u + (uint32_t)lbit4 * 16u;
    }
    uint32_t bA[3];
#pragma unroll
    for (int p = 0; p < 3; p++) {
        int row = warp_n + p * 16 + lrow + lbit4 * 8;
        bA[p] = sbase + OFF_W_B + (uint32_t)row * 144u + (uint32_t)lbit3 * 16u;
    }

    // X: 4 threads/row
    const int xr = tid >> 2;               // 0..63
    const int xq = tid & 3;
    const uint32_t xsts = sbase + OFF_X_B + (uint32_t)xr * 144u + (uint32_t)xq * 16u;
    const float* xsrc_row = X + (size_t)(m0 + xr) * KDIM + xq * 8;

    const uint32_t wdst0 = sbase + OFF_W_B;

    float acc[2][6][4];
#pragma unroll
    for (int mt = 0; mt < 2; mt++)
#pragma unroll
        for (int nt = 0; nt < 6; nt++)
#pragma unroll
            for (int r = 0; r < 4; r++) acc[mt][nt][r] = 0.f;

    float4 xf[2];

    auto convert_sts = [&](uint32_t dOff, int h) {
        uint32_t hw[4];
        hw[0] = cvt_f16x2(xf[0].x, xf[0].y);
        hw[1] = cvt_f16x2(xf[0].z, xf[0].w);
        hw[2] = cvt_f16x2(xf[1].x, xf[1].y);
        hw[3] = cvt_f16x2(xf[1].z, xf[1].w);
        asm volatile("st.shared.v4.b32 [%0], {%1,%2,%3,%4};" ::
                     "r"(xsts + dOff + (uint32_t)h * 64u),
                     "r"(hw[0]), "r"(hw[1]), "r"(hw[2]), "r"(hw[3]));
    };

    auto ldg_x = [&](int c, int h) {
        const float4* p = reinterpret_cast<const float4*>(
            xsrc_row + (size_t)c * BK + h * 32);
        xf[0] = p[0]; xf[1] = p[1];
    };

    // issue W chunk c into W buffer at byte offset `dOff` (one commit group)
    auto issue_w = [&](int c, uint32_t dOff) {
        const size_t koff = (size_t)c * BK;
#pragma unroll
        for (int r = 0; r < 6; r++) {
            int u = tid + r * 256;
            int n = u >> 3, q = u & 7;
            uint32_t d = wdst0 + dOff + (uint32_t)n * 144u + (uint32_t)q * 16u;
            cp_async16(d, g_Wt + (size_t)n * KDIM + koff + q * 8);
        }
        cp_commit();
    };

    // --- prologue: W(0)->buf0, W(1)->buf1; X(0) full; X(1,h0) regs ---
    issue_w(0, 0);
    issue_w(1, WBUF_STRIDE_B);
    ldg_x(0, 0); convert_sts(0, 0);
    ldg_x(0, 1); convert_sts(0, 1);
    ldg_x(1, 0);
    asm volatile("cp.async.wait_group 1;\n" ::: "memory");   // W(0) landed
    __syncthreads();

    uint32_t wCur = 0, wNext = WBUF_STRIDE_B, wFill = 2u * WBUF_STRIDE_B;

#pragma unroll 1
    for (int c = 0; c < NCHUNK; ++c) {
        const uint32_t xOff  = (uint32_t)(c & 1) * XBUF_STRIDE_B;
        const uint32_t xNext = (uint32_t)((c + 1) & 1) * XBUF_STRIDE_B;

        // stage next X (h0), fetch X(c+1,h1), prefetch W(c+2)
        if (c + 1 < NCHUNK) {
            convert_sts(xNext, 0);
            ldg_x(c + 1, 1);
        }
        if (c + 2 < NCHUNK) issue_w(c + 2, wFill);

        // compute kk2 = 0,1
#pragma unroll
        for (int kk2 = 0; kk2 < 2; kk2++) {
            const uint32_t kb = kk2 * 32;
            uint32_t ah[2][4], bh[3][4];
#pragma unroll
            for (int mt = 0; mt < 2; mt++) ldsm4(ah[mt], aA[mt] + xOff + kb);
#pragma unroll
            for (int p = 0; p < 3; p++)    ldsm4(bh[p], bA[p] + wCur + kb);
#pragma unroll
            for (int mt = 0; mt < 2; mt++)
#pragma unroll
                for (int nt = 0; nt < 6; nt++)
                    mma16816(acc[mt][nt], ah[mt],
                             bh[nt >> 1][(nt & 1) * 2], bh[nt >> 1][(nt & 1) * 2 + 1]);
        }

        // stage next X (h1), prefetch X(c+2,h0)
        if (c + 1 < NCHUNK) {
            convert_sts(xNext, 1);
            if (c + 2 < NCHUNK) ldg_x(c + 2, 0);
        }

        // compute kk2 = 2,3
#pragma unroll
        for (int kk2 = 2; kk2 < 4; kk2++) {
            const uint32_t kb = kk2 * 32;
            uint32_t ah[2][4], bh[3][4];
#pragma unroll
            for (int mt = 0; mt < 2; mt++) ldsm4(ah[mt], aA[mt] + xOff + kb);
#pragma unroll
            for (int p = 0; p < 3; p++)    ldsm4(bh[p], bA[p] + wCur + kb);
#pragma unroll
            for (int mt = 0; mt < 2; mt++)
#pragma unroll
                for (int nt = 0; nt < 6; nt++)
                    mma16816(acc[mt][nt], ah[mt],
                             bh[nt >> 1][(nt & 1) * 2], bh[nt >> 1][(nt & 1) * 2 + 1]);
        }

        // tail: ensure W(c+1) landed (issued a full chunk ago); X(c+1) visible
        if (c + 1 < NCHUNK) {
            if (c + 2 < NCHUNK) {
                asm volatile("cp.async.wait_group 1;\n" ::: "memory");
            } else {
                asm volatile("cp.async.wait_group 0;\n" ::: "memory");
            }
            __syncthreads();
        }

        // rotate W buffers
        uint32_t tmp = wCur; wCur = wNext; wNext = wFill; wFill = tmp;
    }

    // epilogue: write q|k|v to scratch
#pragma unroll
    for (int mt = 0; mt < 2; mt++) {
#pragma unroll
        for (int nt = 0; nt < 6; nt++) {
            int r  = m0 + warp_m + mt * 16 + g;
            int cn = warp_n + nt * 8 + 2 * tig;
            float2 v0 = make_float2(acc[mt][nt][0], acc[mt][nt][1]);
            float2 v1 = make_float2(acc[mt][nt][2], acc[mt][nt][3]);
            *reinterpret_cast<float2*>(&g_qkv[(size_t)r * NTOT + cn]) = v0;
            *reinterpret_cast<float2*>(&g_qkv[(size_t)(r + 8) * NTOT + cn]) = v1;
        }
    }
}

// ---------------------------------------------------------------- attention
// No max-subtraction (softmax shift-invariant; |q·k| within fp32 exp range).
__global__ void __launch_bounds__(256)
attn_kernel(float* __restrict__ out) {
    __shared__ float4 ks[4][16];
    __shared__ float4 vs[4][16];
    const int tid = threadIdx.x;
    const int tl = tid >> 6;
    const int i  = tid & 63;
    const size_t tok = (size_t)blockIdx.x * 4 + tl;
    const float* base = g_qkv + tok * NTOT;

    float q = base[i] * 1.4426950408889634f;   // fold log2(e)
    reinterpret_cast<float*>(&ks[tl][0])[i] = base[64 + i];
    reinterpret_cast<float*>(&vs[tl][0])[i] = base[128 + i];
    __syncthreads();

    float s = 0.f, num = 0.f;
#pragma unroll
    for (int j4 = 0; j4 < 16; j4++) {
        float4 k4 = ks[tl][j4];
        float4 v4 = vs[tl][j4];
        float e0 = ex2f(q * k4.x);
        float e1 = ex2f(q * k4.y);
        float e2 = ex2f(q * k4.z);
        float e3 = ex2f(q * k4.w);
        s += (e0 + e1) + (e2 + e3);
        num = fmaf(e0, v4.x, num);
        num = fmaf(e1, v4.y, num);
        num = fmaf(e2, v4.z, num);
        num = fmaf(e3, v4.w, num);
    }
    out[tok * 64 + i] = num / s;
}

// ----------------------------------------------------------------
extern "C" void kernel_launch(void* const* d_in, const int* in_sizes, int n_in,
                              void* d_out, int out_size) {
    const float* X  = (const float*)d_in[0];
    const float* Wq = (const float*)d_in[1];
    const float* Wk = (const float*)d_in[2];
    const float* Wv = (const float*)d_in[3];
    float* out = (float*)d_out;

    cudaFuncSetAttribute(qkv_gemm, cudaFuncAttributeMaxDynamicSharedMemorySize,
                         SMEM_BYTES);

    prep_w<<<192, 256>>>(Wq, Wk, Wv);
    qkv_gemm<<<M_TOK / BM, 256, SMEM_BYTES>>>(X);
    attn_kernel<<<M_TOK / 4, 256>>>(out);
}